// round 2
// baseline (speedup 1.0000x reference)
#include <cuda_runtime.h>
#include <math.h>

#define Nn 100000
#define Ee 1600000
#define Gg 64
#define Cc 40
#define EPSb 1e-5f

// ---------------- scratch (static __device__, allowed) ----------------
__device__ __align__(128) float g_deg[Nn];
__device__ __align__(128) int   g_cnt[Nn];
__device__ __align__(128) int   g_off[Nn];
__device__ __align__(128) int   g_cur[Nn];
__device__ __align__(128) int   g_rowS[Ee];
__device__ __align__(128) float g_wS[Ee];
__device__ __align__(128) float g_hcat1[Nn * 64];            // [h0|h1|h2|h3] width 16 each
__device__ __align__(128) float g_hcat2[(size_t)Nn * 512];   // [h0|h1|h2|h3] width 128 each
__device__ __align__(128) float g_xcat[(size_t)Nn * 256];    // [x1 | x2]
__device__ __align__(128) float g_hlin[(size_t)Nn * 256];
__device__ __align__(128) float g_stats[1024];               // s1(256) s2(256) sl(512)
__device__ __align__(128) float g_pooled[Gg * 256];
__device__ __align__(128) float g_f1[Gg * 256];
__device__ __align__(128) float g_f2[Gg * 128];

// ---------------- helpers ----------------
__device__ __forceinline__ unsigned long long pk2(float x, float y) {
    unsigned long long r;
    asm("mov.b64 %0, {%1,%2};" : "=l"(r) : "f"(x), "f"(y));
    return r;
}
__device__ __forceinline__ void fma2(unsigned long long& d, unsigned long long a, unsigned long long b) {
    asm("fma.rn.f32x2 %0, %1, %2, %0;" : "+l"(d) : "l"(a), "l"(b));
}
__device__ __forceinline__ float2 up2(unsigned long long v) {
    float2 f;
    asm("mov.b64 {%0,%1}, %2;" : "=f"(f.x), "=f"(f.y) : "l"(v));
    return f;
}
__device__ __forceinline__ void atomicMaxF(float* a, float v) {
    if (v >= 0.f) atomicMax((int*)a, __float_as_int(v));
    else          atomicMin((unsigned int*)a, __float_as_uint(v));
}

// ---------------- graph preprocessing ----------------
__global__ __launch_bounds__(256) void k_deg_hist(const int* __restrict__ col,
                                                  const float* __restrict__ ea) {
    int e = blockIdx.x * blockDim.x + threadIdx.x;
    if (e >= Ee) return;
    int c = col[e];
    atomicAdd(&g_deg[c], ea[e]);
    atomicAdd(&g_cnt[c], 1);
}

__global__ __launch_bounds__(256) void k_scan() {  // single-block exclusive scan
    __shared__ int ss[256];
    const int CH = (Nn + 255) / 256;
    int t = threadIdx.x;
    int base = t * CH;
    int s = 0;
    for (int i = 0; i < CH; i++) { int idx = base + i; if (idx < Nn) s += g_cnt[idx]; }
    ss[t] = s;
    __syncthreads();
    int own = s;
    for (int o = 1; o < 256; o <<= 1) {
        int v = (t >= o) ? ss[t - o] : 0;
        __syncthreads();
        ss[t] += v;
        __syncthreads();
    }
    int run = ss[t] - own;  // exclusive prefix
    for (int i = 0; i < CH; i++) {
        int idx = base + i;
        if (idx < Nn) { g_off[idx] = run; run += g_cnt[idx]; }
    }
}

__global__ __launch_bounds__(256) void k_scatter(const int* __restrict__ row,
                                                 const int* __restrict__ col,
                                                 const float* __restrict__ ea) {
    int e = blockIdx.x * blockDim.x + threadIdx.x;
    if (e >= Ee) return;
    int r = row[e], c = col[e];
    float dr = g_deg[r], dc = g_deg[c];
    float ir = dr > 0.f ? rsqrtf(dr) : 0.f;
    float ic = dc > 0.f ? rsqrtf(dc) : 0.f;
    float w = ir * ea[e] * ic;
    int p = g_off[c] + atomicAdd(&g_cur[c], 1);
    g_rowS[p] = r;
    g_wS[p] = w;
}

__global__ __launch_bounds__(256) void k_copyx(const float* __restrict__ x) {
    int i = blockIdx.x * blockDim.x + threadIdx.x;
    if (i >= Nn * 16) return;
    int n = i >> 4, j = i & 15;
    g_hcat1[n * 64 + j] = x[i];
}

// CSR gather propagation: TPN threads per node, each thread owns 4 features
template <int TPN>
__global__ __launch_bounds__(256) void k_prop(float* __restrict__ hbase, int stride,
                                              int so, int dofs) {
    int gid = blockIdx.x * blockDim.x + threadIdx.x;
    int node = gid / TPN;
    int part = gid % TPN;
    if (node >= Nn) return;
    int s = g_off[node];
    int e = s + g_cnt[node];
    float4 acc = make_float4(0.f, 0.f, 0.f, 0.f);
    int so4 = so + part * 4;
    for (int i = s; i < e; i++) {
        int r = __ldg(&g_rowS[i]);
        float w = __ldg(&g_wS[i]);
        const float4 v = *reinterpret_cast<const float4*>(hbase + r * stride + so4);
        acc.x = fmaf(w, v.x, acc.x);
        acc.y = fmaf(w, v.y, acc.y);
        acc.z = fmaf(w, v.z, acc.z);
        acc.w = fmaf(w, v.w, acc.w);
    }
    *reinterpret_cast<float4*>(hbase + node * stride + dofs + part * 4) = acc;
}

// ---------------- GEMM: C[M,Nc] = relu(A[M,Kd] @ B[Kd,Nc] + bias) ----------------
// 64x64 tile, BK=32, 128 threads, thread tile 4x8 using packed f32x2 FFMA
__global__ __launch_bounds__(128) void k_gemm_bias_relu(
    const float* __restrict__ A, int lda,
    const float* __restrict__ B, const float* __restrict__ bias,
    float* __restrict__ C, int ldc, int M, int Kd, int Nc) {
    __shared__ __align__(16) float As[32][64];  // [k][m] transposed
    __shared__ __align__(16) float Bs[32][64];  // [k][n]
    int row0 = blockIdx.x * 64, col0 = blockIdx.y * 64;
    int tid = threadIdx.x;
    int ty = tid >> 3;   // 0..15 -> rows ty*4..+3
    int tx = tid & 7;    // 0..7  -> cols tx*8..+7
    unsigned long long acc[4][4];
#pragma unroll
    for (int i = 0; i < 4; i++)
#pragma unroll
        for (int j = 0; j < 4; j++) acc[i][j] = 0ULL;

    for (int k0 = 0; k0 < Kd; k0 += 32) {
#pragma unroll
        for (int t0 = 0; t0 < 4; t0++) {  // A tile: 64 rows x 8 float4 along k
            int t = tid + t0 * 128;
            int r = t >> 3, c4 = t & 7;
            float4 v = make_float4(0.f, 0.f, 0.f, 0.f);
            if (row0 + r < M)
                v = *reinterpret_cast<const float4*>(&A[(size_t)(row0 + r) * lda + k0 + c4 * 4]);
            As[c4 * 4 + 0][r] = v.x;
            As[c4 * 4 + 1][r] = v.y;
            As[c4 * 4 + 2][r] = v.z;
            As[c4 * 4 + 3][r] = v.w;
        }
#pragma unroll
        for (int t0 = 0; t0 < 4; t0++) {  // B tile: 32 k x 16 float4 along n
            int t = tid + t0 * 128;
            int kk = t >> 4, c4 = t & 15;
            float4 v = *reinterpret_cast<const float4*>(&B[(size_t)(k0 + kk) * Nc + col0 + c4 * 4]);
            *reinterpret_cast<float4*>(&Bs[kk][c4 * 4]) = v;
        }
        __syncthreads();
#pragma unroll
        for (int k = 0; k < 32; k++) {
            float4 av = *reinterpret_cast<const float4*>(&As[k][ty * 4]);
            unsigned long long a0 = pk2(av.x, av.x), a1 = pk2(av.y, av.y);
            unsigned long long a2 = pk2(av.z, av.z), a3 = pk2(av.w, av.w);
            const ulonglong2* bp = reinterpret_cast<const ulonglong2*>(&Bs[k][tx * 8]);
            ulonglong2 q0 = bp[0], q1 = bp[1];
            fma2(acc[0][0], a0, q0.x); fma2(acc[0][1], a0, q0.y);
            fma2(acc[0][2], a0, q1.x); fma2(acc[0][3], a0, q1.y);
            fma2(acc[1][0], a1, q0.x); fma2(acc[1][1], a1, q0.y);
            fma2(acc[1][2], a1, q1.x); fma2(acc[1][3], a1, q1.y);
            fma2(acc[2][0], a2, q0.x); fma2(acc[2][1], a2, q0.y);
            fma2(acc[2][2], a2, q1.x); fma2(acc[2][3], a2, q1.y);
            fma2(acc[3][0], a3, q0.x); fma2(acc[3][1], a3, q0.y);
            fma2(acc[3][2], a3, q1.x); fma2(acc[3][3], a3, q1.y);
        }
        __syncthreads();
    }
#pragma unroll
    for (int i = 0; i < 4; i++) {
        int r = row0 + ty * 4 + i;
        if (r < M) {
#pragma unroll
            for (int j = 0; j < 4; j++) {
                int c = col0 + tx * 8 + j * 2;
                float2 v = up2(acc[i][j]);
                float o0 = fmaxf(v.x + bias[c], 0.f);
                float o1 = fmaxf(v.y + bias[c + 1], 0.f);
                *reinterpret_cast<float2*>(&C[(size_t)r * ldc + c]) = make_float2(o0, o1);
            }
        }
    }
}

// ---------------- BN stats / apply ----------------
__global__ __launch_bounds__(256) void k_colstats(const float* __restrict__ X, int ldx,
                                                  float* __restrict__ stats) {
    int c = threadIdx.x;
    int Cch = blockDim.x;
    int r0 = blockIdx.x * 256;
    int r1 = min(r0 + 256, Nn);
    float s = 0.f, q = 0.f;
    for (int r = r0; r < r1; r++) {
        float v = X[(size_t)r * ldx + c];
        s += v;
        q = fmaf(v, v, q);
    }
    atomicAdd(&stats[c], s);
    atomicAdd(&stats[Cch + c], q);
}

__global__ __launch_bounds__(256) void k_bn_apply(float* __restrict__ X,
                                                  const float* __restrict__ stats,
                                                  const float* __restrict__ gamma,
                                                  const float* __restrict__ beta,
                                                  float* __restrict__ dst2) {
    int idx = blockIdx.x * blockDim.x + threadIdx.x;
    if (idx >= Nn * 128) return;
    int n = idx >> 7, c = idx & 127;
    float m = stats[c] * (1.f / Nn);
    float var = stats[128 + c] * (1.f / Nn) - m * m;
    float sc = gamma[c] * rsqrtf(var + EPSb);
    float sh = beta[c] - m * sc;
    float y = fmaf(X[(size_t)n * 256 + c], sc, sh);
    X[(size_t)n * 256 + c] = y;
    if (dst2) dst2[(size_t)n * 512 + c] = y;  // h0 for conv2
}

// ---------------- pooling (fused BN of lin1 output) ----------------
__global__ __launch_bounds__(256) void k_pool_init() {
    int i = blockIdx.x * blockDim.x + threadIdx.x;
    if (i < Gg * 256) g_pooled[i] = -INFINITY;
}

__global__ __launch_bounds__(256) void k_pool(const int* __restrict__ batch,
                                              const float* __restrict__ gamma,
                                              const float* __restrict__ beta) {
    int c = threadIdx.x;  // 256 channels
    int r0 = blockIdx.x * 128;
    int r1 = min(r0 + 128, Nn);
    float s = g_stats[512 + c], q = g_stats[768 + c];
    float m = s * (1.f / Nn), var = q * (1.f / Nn) - m * m;
    float sc = gamma[c] * rsqrtf(var + EPSb);
    float sh = beta[c] - m * sc;
    float cur = -INFINITY;
    int curg = batch[r0];
    for (int r = r0; r < r1; r++) {
        int g = batch[r];
        if (g != curg) {
            atomicMaxF(&g_pooled[curg * 256 + c], cur);
            cur = -INFINITY;
            curg = g;
        }
        float v = fmaf(g_hlin[(size_t)r * 256 + c], sc, sh);
        cur = fmaxf(cur, v);
    }
    atomicMaxF(&g_pooled[curg * 256 + c], cur);
}

// ---------------- head ----------------
__global__ __launch_bounds__(128) void k_head_gemm_relu(const float* __restrict__ A,
                                                        const float* __restrict__ B,
                                                        const float* __restrict__ bias,
                                                        float* __restrict__ Cmat,
                                                        int Kd, int Nc) {
    int idx = blockIdx.x * blockDim.x + threadIdx.x;
    if (idx >= Gg * Nc) return;
    int g = idx / Nc, c = idx - g * Nc;
    float acc = bias[c];
    for (int k = 0; k < Kd; k++) acc = fmaf(A[g * Kd + k], B[k * Nc + c], acc);
    Cmat[idx] = fmaxf(acc, 0.f);
}

__global__ __launch_bounds__(256) void k_head_bn(float* __restrict__ X,
                                                 const float* __restrict__ gamma,
                                                 const float* __restrict__ beta, int Cch) {
    int c = threadIdx.x;
    if (c >= Cch) return;
    float s = 0.f, q = 0.f;
    for (int g = 0; g < Gg; g++) {
        float v = X[g * Cch + c];
        s += v;
        q += v * v;
    }
    float m = s / Gg;
    float var = q / Gg - m * m;
    float sc = gamma[c] * rsqrtf(var + EPSb);
    float sh = beta[c] - m * sc;
    for (int g = 0; g < Gg; g++) X[g * Cch + c] = X[g * Cch + c] * sc + sh;
}

__global__ __launch_bounds__(64) void k_logits(const float* __restrict__ Wf3,
                                               const float* __restrict__ bf3,
                                               float* __restrict__ out) {
    int g = blockIdx.x;
    int c = threadIdx.x;  // 64 threads, first 40 active
    __shared__ float sl[64];
    __shared__ float s_m, s_l;
    float v = -INFINITY;
    if (c < Cc) {
        float acc = bf3[c];
        for (int k = 0; k < 128; k++) acc = fmaf(g_f2[g * 128 + k], Wf3[k * Cc + c], acc);
        v = acc;
    }
    sl[c] = v;
    __syncthreads();
    if (c == 0) {
        float m = -INFINITY;
        for (int i = 0; i < Cc; i++) m = fmaxf(m, sl[i]);
        float s = 0.f;
        for (int i = 0; i < Cc; i++) s += expf(sl[i] - m);
        s_m = m;
        s_l = logf(s);
    }
    __syncthreads();
    if (c < Cc) out[g * Cc + c] = sl[c] - s_m - s_l;
}

// ---------------- launch ----------------
extern "C" void kernel_launch(void* const* d_in, const int* in_sizes, int n_in,
                              void* d_out, int out_size) {
    const float* x      = (const float*)d_in[0];
    const int*   ei     = (const int*)d_in[1];
    const float* ea     = (const float*)d_in[2];
    const int*   batch  = (const int*)d_in[3];
    const float* W1     = (const float*)d_in[4];
    const float* b1     = (const float*)d_in[5];
    const float* gamma1 = (const float*)d_in[6];
    const float* beta1  = (const float*)d_in[7];
    const float* W2     = (const float*)d_in[8];
    const float* b2     = (const float*)d_in[9];
    const float* gamma2 = (const float*)d_in[10];
    const float* beta2  = (const float*)d_in[11];
    const float* Wl     = (const float*)d_in[12];
    const float* bl     = (const float*)d_in[13];
    const float* gammal = (const float*)d_in[14];
    const float* betal  = (const float*)d_in[15];
    const float* Wf1    = (const float*)d_in[16];
    const float* bf1    = (const float*)d_in[17];
    const float* gammaf1= (const float*)d_in[18];
    const float* betaf1 = (const float*)d_in[19];
    const float* Wf2    = (const float*)d_in[20];
    const float* bf2    = (const float*)d_in[21];
    const float* gammaf2= (const float*)d_in[22];
    const float* betaf2 = (const float*)d_in[23];
    const float* Wf3    = (const float*)d_in[24];
    const float* bf3    = (const float*)d_in[25];
    const int* row = ei;
    const int* col = ei + Ee;
    float* out = (float*)d_out;

    float *p_hcat1, *p_hcat2, *p_xcat, *p_hlin, *p_stats, *p_pooled, *p_f1, *p_f2, *p_deg;
    int *p_cnt, *p_cur;
    cudaGetSymbolAddress((void**)&p_hcat1, g_hcat1);
    cudaGetSymbolAddress((void**)&p_hcat2, g_hcat2);
    cudaGetSymbolAddress((void**)&p_xcat, g_xcat);
    cudaGetSymbolAddress((void**)&p_hlin, g_hlin);
    cudaGetSymbolAddress((void**)&p_stats, g_stats);
    cudaGetSymbolAddress((void**)&p_pooled, g_pooled);
    cudaGetSymbolAddress((void**)&p_f1, g_f1);
    cudaGetSymbolAddress((void**)&p_f2, g_f2);
    cudaGetSymbolAddress((void**)&p_deg, g_deg);
    cudaGetSymbolAddress((void**)&p_cnt, g_cnt);
    cudaGetSymbolAddress((void**)&p_cur, g_cur);

    cudaMemsetAsync(p_deg, 0, Nn * sizeof(float));
    cudaMemsetAsync(p_cnt, 0, Nn * sizeof(int));
    cudaMemsetAsync(p_cur, 0, Nn * sizeof(int));
    cudaMemsetAsync(p_stats, 0, 1024 * sizeof(float));

    // graph preprocessing: degrees -> CSR sorted by col with fused gcn_norm
    k_deg_hist<<<(Ee + 255) / 256, 256>>>(col, ea);
    k_scan<<<1, 256>>>();
    k_scatter<<<(Ee + 255) / 256, 256>>>(row, col, ea);

    // conv1: propagate width-16 features, one wide GEMM
    k_copyx<<<(Nn * 16 + 255) / 256, 256>>>(x);
    k_prop<4><<<(Nn * 4 + 255) / 256, 256>>>(p_hcat1, 64, 0, 16);
    k_prop<4><<<(Nn * 4 + 255) / 256, 256>>>(p_hcat1, 64, 16, 32);
    k_prop<4><<<(Nn * 4 + 255) / 256, 256>>>(p_hcat1, 64, 32, 48);
    dim3 gc((Nn + 63) / 64, 2);
    k_gemm_bias_relu<<<gc, 128>>>(p_hcat1, 64, W1, b1, p_xcat, 256, Nn, 64, 128);
    k_colstats<<<(Nn + 255) / 256, 128>>>(p_xcat, 256, p_stats);
    k_bn_apply<<<(Nn * 128 + 255) / 256, 256>>>(p_xcat, p_stats, gamma1, beta1, p_hcat2);

    // conv2: propagate width-128 features, one wide GEMM
    k_prop<32><<<(Nn * 32 + 255) / 256, 256>>>(p_hcat2, 512, 0, 128);
    k_prop<32><<<(Nn * 32 + 255) / 256, 256>>>(p_hcat2, 512, 128, 256);
    k_prop<32><<<(Nn * 32 + 255) / 256, 256>>>(p_hcat2, 512, 256, 384);
    k_gemm_bias_relu<<<gc, 128>>>(p_hcat2, 512, W2, b2, p_xcat + 128, 256, Nn, 512, 128);
    k_colstats<<<(Nn + 255) / 256, 128>>>(p_xcat + 128, 256, p_stats + 256);
    k_bn_apply<<<(Nn * 128 + 255) / 256, 256>>>(p_xcat + 128, p_stats + 256, gamma2, beta2, nullptr);

    // lin1 on concat [x1|x2]
    dim3 gl((Nn + 63) / 64, 4);
    k_gemm_bias_relu<<<gl, 128>>>(p_xcat, 256, Wl, bl, p_hlin, 256, Nn, 256, 256);
    k_colstats<<<(Nn + 255) / 256, 256>>>(p_hlin, 256, p_stats + 512);

    // BN(lin1) fused into global max pool
    k_pool_init<<<(Gg * 256 + 255) / 256, 256>>>();
    k_pool<<<(Nn + 127) / 128, 256>>>(batch, gammal, betal);

    // head
    k_head_gemm_relu<<<(Gg * 256 + 127) / 128, 128>>>(p_pooled, Wf1, bf1, p_f1, 256, 256);
    k_head_bn<<<1, 256>>>(p_f1, gammaf1, betaf1, 256);
    k_head_gemm_relu<<<(Gg * 128 + 127) / 128, 128>>>(p_f1, Wf2, bf2, p_f2, 256, 128);
    k_head_bn<<<1, 128>>>(p_f2, gammaf2, betaf2, 128);
    k_logits<<<Gg, 64>>>(Wf3, bf3, out);
}

// round 4
// speedup vs baseline: 1.4195x; 1.4195x over previous
#include <cuda_runtime.h>
#include <math.h>

#define Nn 100000
#define Ee 1600000
#define Gg 64
#define Cc 40
#define EPSb 1e-5f

// ---------------- scratch ----------------
__device__ __align__(128) float g_deg[Nn];
__device__ __align__(128) int   g_cnt[Nn];
__device__ __align__(128) int   g_off[Nn];
__device__ __align__(128) int   g_cur[Nn];
__device__ __align__(128) int   g_rowS[Ee];
__device__ __align__(128) float g_wS[Ee];
__device__ __align__(128) float g_hcat1[Nn * 64];
__device__ __align__(128) float g_hcat2[(size_t)Nn * 512];
__device__ __align__(128) float g_xcat[(size_t)Nn * 256];   // [x1raw | x2raw] (relu'd, pre-BN)
__device__ __align__(128) float g_stats[1024];              // s1 q1 s2 q2 sl(256) ql(256)
__device__ __align__(128) float g_bnsc[256];
__device__ __align__(128) float g_bnsh[256];
__device__ __align__(128) int   g_pmax[Gg * 256];
__device__ __align__(128) int   g_pmin[Gg * 256];
__device__ __align__(128) float g_pooled[Gg * 256];
__device__ __align__(128) float g_f1[Gg * 256];
__device__ __align__(128) float g_f2[Gg * 128];

// ---------------- helpers ----------------
__device__ __forceinline__ unsigned long long pk2(float x, float y) {
    unsigned long long r;
    asm("mov.b64 %0, {%1,%2};" : "=l"(r) : "f"(x), "f"(y));
    return r;
}
__device__ __forceinline__ void fma2(unsigned long long& d, unsigned long long a, unsigned long long b) {
    asm("fma.rn.f32x2 %0, %1, %2, %0;" : "+l"(d) : "l"(a), "l"(b));
}
__device__ __forceinline__ float2 up2(unsigned long long v) {
    float2 f;
    asm("mov.b64 {%0,%1}, %2;" : "=f"(f.x), "=f"(f.y) : "l"(v));
    return f;
}

// ---------------- graph preprocessing ----------------
__global__ __launch_bounds__(256) void k_deg_hist(const int* __restrict__ col,
                                                  const float* __restrict__ ea) {
    int e = blockIdx.x * blockDim.x + threadIdx.x;
    if (e >= Ee) return;
    int c = col[e];
    atomicAdd(&g_deg[c], ea[e]);
    atomicAdd(&g_cnt[c], 1);
}

__global__ __launch_bounds__(256) void k_scan() {
    __shared__ int ss[256];
    const int CH = (Nn + 255) / 256;
    int t = threadIdx.x;
    int base = t * CH;
    int s = 0;
    for (int i = 0; i < CH; i++) { int idx = base + i; if (idx < Nn) s += g_cnt[idx]; }
    ss[t] = s;
    __syncthreads();
    int own = s;
    for (int o = 1; o < 256; o <<= 1) {
        int v = (t >= o) ? ss[t - o] : 0;
        __syncthreads();
        ss[t] += v;
        __syncthreads();
    }
    int run = ss[t] - own;
    for (int i = 0; i < CH; i++) {
        int idx = base + i;
        if (idx < Nn) { g_off[idx] = run; run += g_cnt[idx]; }
    }
}

__global__ __launch_bounds__(256) void k_scatter(const int* __restrict__ row,
                                                 const int* __restrict__ col,
                                                 const float* __restrict__ ea) {
    int e = blockIdx.x * blockDim.x + threadIdx.x;
    if (e >= Ee) return;
    int r = row[e], c = col[e];
    float dr = g_deg[r], dc = g_deg[c];
    float ir = dr > 0.f ? rsqrtf(dr) : 0.f;
    float ic = dc > 0.f ? rsqrtf(dc) : 0.f;
    float w = ir * ea[e] * ic;
    int p = g_off[c] + atomicAdd(&g_cur[c], 1);
    g_rowS[p] = r;
    g_wS[p] = w;
}

__global__ __launch_bounds__(256) void k_copyx(const float* __restrict__ x) {
    int i = blockIdx.x * blockDim.x + threadIdx.x;
    if (i >= Nn * 16) return;
    int n = i >> 4, j = i & 15;
    g_hcat1[n * 64 + j] = x[i];
}

// CSR gather propagation: TPN threads/node, 4 features each
template <int TPN>
__global__ __launch_bounds__(256) void k_prop(float* __restrict__ hbase, int stride,
                                              int so, int dofs) {
    int gid = blockIdx.x * blockDim.x + threadIdx.x;
    int node = gid / TPN;
    int part = gid % TPN;
    if (node >= Nn) return;
    int s = g_off[node];
    int e = s + g_cnt[node];
    float4 acc = make_float4(0.f, 0.f, 0.f, 0.f);
    int so4 = so + part * 4;
    for (int i = s; i < e; i++) {
        int r = __ldg(&g_rowS[i]);
        float w = __ldg(&g_wS[i]);
        const float4 v = *reinterpret_cast<const float4*>(hbase + (size_t)r * stride + so4);
        acc.x = fmaf(w, v.x, acc.x);
        acc.y = fmaf(w, v.y, acc.y);
        acc.z = fmaf(w, v.z, acc.z);
        acc.w = fmaf(w, v.w, acc.w);
    }
    *reinterpret_cast<float4*>(hbase + (size_t)node * stride + dofs + part * 4) = acc;
}

// =====================================================================
// GEMM 128x128 tile, BK=16, 256 threads, 8x8 micro-tile (f32x2 FFMA)
// Epilogue: relu(out+bias) -> store C + column stats (sum, sumsq)
// =====================================================================
__global__ __launch_bounds__(256) void k_gemm_conv(
    const float* __restrict__ A, int lda,
    const float* __restrict__ B, const float* __restrict__ bias,
    float* __restrict__ C, int Kd, int Nc,
    float* __restrict__ sS, float* __restrict__ sQ) {
    __shared__ __align__(16) float As[16][132];
    __shared__ __align__(16) float Bs[16][128];
    int row0 = blockIdx.x * 128, col0 = blockIdx.y * 128;
    int tid = threadIdx.x;
    int ty = tid >> 4, tx = tid & 15;
    unsigned long long acc[8][4];
#pragma unroll
    for (int i = 0; i < 8; i++)
#pragma unroll
        for (int j = 0; j < 4; j++) acc[i][j] = 0ULL;

    for (int k0 = 0; k0 < Kd; k0 += 16) {
#pragma unroll
        for (int i = 0; i < 2; i++) {
            int t = tid + i * 256;
            int r = t >> 2, c4 = t & 3;
            float4 v = make_float4(0.f, 0.f, 0.f, 0.f);
            if (row0 + r < Nn)
                v = *reinterpret_cast<const float4*>(&A[(size_t)(row0 + r) * lda + k0 + c4 * 4]);
            As[c4 * 4 + 0][r] = v.x;
            As[c4 * 4 + 1][r] = v.y;
            As[c4 * 4 + 2][r] = v.z;
            As[c4 * 4 + 3][r] = v.w;
        }
#pragma unroll
        for (int i = 0; i < 2; i++) {
            int t = tid + i * 256;
            int kk = t >> 5, c4 = t & 31;
            *reinterpret_cast<float4*>(&Bs[kk][c4 * 4]) =
                *reinterpret_cast<const float4*>(&B[(size_t)(k0 + kk) * Nc + col0 + c4 * 4]);
        }
        __syncthreads();
#pragma unroll
        for (int k = 0; k < 16; k++) {
            float4 a0 = *reinterpret_cast<const float4*>(&As[k][ty * 8]);
            float4 a1 = *reinterpret_cast<const float4*>(&As[k][ty * 8 + 4]);
            unsigned long long A0 = pk2(a0.x, a0.x), A1 = pk2(a0.y, a0.y);
            unsigned long long A2 = pk2(a0.z, a0.z), A3 = pk2(a0.w, a0.w);
            unsigned long long A4 = pk2(a1.x, a1.x), A5 = pk2(a1.y, a1.y);
            unsigned long long A6 = pk2(a1.z, a1.z), A7 = pk2(a1.w, a1.w);
            const ulonglong2* bp = reinterpret_cast<const ulonglong2*>(&Bs[k][tx * 8]);
            ulonglong2 q0 = bp[0], q1 = bp[1];
            fma2(acc[0][0], A0, q0.x); fma2(acc[0][1], A0, q0.y); fma2(acc[0][2], A0, q1.x); fma2(acc[0][3], A0, q1.y);
            fma2(acc[1][0], A1, q0.x); fma2(acc[1][1], A1, q0.y); fma2(acc[1][2], A1, q1.x); fma2(acc[1][3], A1, q1.y);
            fma2(acc[2][0], A2, q0.x); fma2(acc[2][1], A2, q0.y); fma2(acc[2][2], A2, q1.x); fma2(acc[2][3], A2, q1.y);
            fma2(acc[3][0], A3, q0.x); fma2(acc[3][1], A3, q0.y); fma2(acc[3][2], A3, q1.x); fma2(acc[3][3], A3, q1.y);
            fma2(acc[4][0], A4, q0.x); fma2(acc[4][1], A4, q0.y); fma2(acc[4][2], A4, q1.x); fma2(acc[4][3], A4, q1.y);
            fma2(acc[5][0], A5, q0.x); fma2(acc[5][1], A5, q0.y); fma2(acc[5][2], A5, q1.x); fma2(acc[5][3], A5, q1.y);
            fma2(acc[6][0], A6, q0.x); fma2(acc[6][1], A6, q0.y); fma2(acc[6][2], A6, q1.x); fma2(acc[6][3], A6, q1.y);
            fma2(acc[7][0], A7, q0.x); fma2(acc[7][1], A7, q0.y); fma2(acc[7][2], A7, q1.x); fma2(acc[7][3], A7, q1.y);
        }
        __syncthreads();
    }
    // epilogue: relu + store + per-thread column stats
    float s[8], q[8];
#pragma unroll
    for (int j = 0; j < 8; j++) { s[j] = 0.f; q[j] = 0.f; }
#pragma unroll
    for (int i = 0; i < 8; i++) {
        int row = row0 + ty * 8 + i;
        if (row < Nn) {
#pragma unroll
            for (int jj = 0; jj < 4; jj++) {
                float2 v = up2(acc[i][jj]);
                int c = tx * 8 + jj * 2;
                float o0 = fmaxf(v.x + bias[col0 + c], 0.f);
                float o1 = fmaxf(v.y + bias[col0 + c + 1], 0.f);
                *reinterpret_cast<float2*>(&C[(size_t)row * 256 + col0 + c]) = make_float2(o0, o1);
                s[jj * 2] += o0; s[jj * 2 + 1] += o1;
                q[jj * 2] = fmaf(o0, o0, q[jj * 2]);
                q[jj * 2 + 1] = fmaf(o1, o1, q[jj * 2 + 1]);
            }
        }
    }
    __syncthreads();
    float* red = &As[0][0];  // [0:128] sums, [128:256] sumsq
    red[tid] = 0.f;
    __syncthreads();
#pragma unroll
    for (int j = 0; j < 8; j++) {
        atomicAdd(&red[tx * 8 + j], s[j]);
        atomicAdd(&red[128 + tx * 8 + j], q[j]);
    }
    __syncthreads();
    if (tid < 128) atomicAdd(&sS[col0 + tid], red[tid]);
    else           atomicAdd(&sQ[col0 + tid - 128], red[tid]);
}

// =====================================================================
// lin1 GEMM: BN applied to A columns at load; epilogue = relu + stats +
// per-graph max/min pool (no C store).
// =====================================================================
__global__ __launch_bounds__(256) void k_gemm_lin(
    const float* __restrict__ A,
    const float* __restrict__ B, const float* __restrict__ bias,
    const int* __restrict__ batch,
    float* __restrict__ sS, float* __restrict__ sQ) {
    const int Kd = 256, Nc = 256, lda = 256;
    __shared__ __align__(16) float As[16][132];
    __shared__ __align__(16) float Bs[16][128];
    __shared__ float sbn_sc[256], sbn_sh[256];
    int row0 = blockIdx.x * 128, col0 = blockIdx.y * 128;
    int tid = threadIdx.x;
    int ty = tid >> 4, tx = tid & 15;
    sbn_sc[tid] = g_bnsc[tid];
    sbn_sh[tid] = g_bnsh[tid];
    __syncthreads();
    unsigned long long acc[8][4];
#pragma unroll
    for (int i = 0; i < 8; i++)
#pragma unroll
        for (int j = 0; j < 4; j++) acc[i][j] = 0ULL;

    for (int k0 = 0; k0 < Kd; k0 += 16) {
#pragma unroll
        for (int i = 0; i < 2; i++) {
            int t = tid + i * 256;
            int r = t >> 2, c4 = t & 3;
            float4 v = make_float4(0.f, 0.f, 0.f, 0.f);
            if (row0 + r < Nn) {
                v = *reinterpret_cast<const float4*>(&A[(size_t)(row0 + r) * lda + k0 + c4 * 4]);
                int kc = k0 + c4 * 4;
                v.x = fmaf(v.x, sbn_sc[kc],     sbn_sh[kc]);
                v.y = fmaf(v.y, sbn_sc[kc + 1], sbn_sh[kc + 1]);
                v.z = fmaf(v.z, sbn_sc[kc + 2], sbn_sh[kc + 2]);
                v.w = fmaf(v.w, sbn_sc[kc + 3], sbn_sh[kc + 3]);
            }
            As[c4 * 4 + 0][r] = v.x;
            As[c4 * 4 + 1][r] = v.y;
            As[c4 * 4 + 2][r] = v.z;
            As[c4 * 4 + 3][r] = v.w;
        }
#pragma unroll
        for (int i = 0; i < 2; i++) {
            int t = tid + i * 256;
            int kk = t >> 5, c4 = t & 31;
            *reinterpret_cast<float4*>(&Bs[kk][c4 * 4]) =
                *reinterpret_cast<const float4*>(&B[(size_t)(k0 + kk) * Nc + col0 + c4 * 4]);
        }
        __syncthreads();
#pragma unroll
        for (int k = 0; k < 16; k++) {
            float4 a0 = *reinterpret_cast<const float4*>(&As[k][ty * 8]);
            float4 a1 = *reinterpret_cast<const float4*>(&As[k][ty * 8 + 4]);
            unsigned long long A0 = pk2(a0.x, a0.x), A1 = pk2(a0.y, a0.y);
            unsigned long long A2 = pk2(a0.z, a0.z), A3 = pk2(a0.w, a0.w);
            unsigned long long A4 = pk2(a1.x, a1.x), A5 = pk2(a1.y, a1.y);
            unsigned long long A6 = pk2(a1.z, a1.z), A7 = pk2(a1.w, a1.w);
            const ulonglong2* bp = reinterpret_cast<const ulonglong2*>(&Bs[k][tx * 8]);
            ulonglong2 q0 = bp[0], q1 = bp[1];
            fma2(acc[0][0], A0, q0.x); fma2(acc[0][1], A0, q0.y); fma2(acc[0][2], A0, q1.x); fma2(acc[0][3], A0, q1.y);
            fma2(acc[1][0], A1, q0.x); fma2(acc[1][1], A1, q0.y); fma2(acc[1][2], A1, q1.x); fma2(acc[1][3], A1, q1.y);
            fma2(acc[2][0], A2, q0.x); fma2(acc[2][1], A2, q0.y); fma2(acc[2][2], A2, q1.x); fma2(acc[2][3], A2, q1.y);
            fma2(acc[3][0], A3, q0.x); fma2(acc[3][1], A3, q0.y); fma2(acc[3][2], A3, q1.x); fma2(acc[3][3], A3, q1.y);
            fma2(acc[4][0], A4, q0.x); fma2(acc[4][1], A4, q0.y); fma2(acc[4][2], A4, q1.x); fma2(acc[4][3], A4, q1.y);
            fma2(acc[5][0], A5, q0.x); fma2(acc[5][1], A5, q0.y); fma2(acc[5][2], A5, q1.x); fma2(acc[5][3], A5, q1.y);
            fma2(acc[6][0], A6, q0.x); fma2(acc[6][1], A6, q0.y); fma2(acc[6][2], A6, q1.x); fma2(acc[6][3], A6, q1.y);
            fma2(acc[7][0], A7, q0.x); fma2(acc[7][1], A7, q0.y); fma2(acc[7][2], A7, q1.x); fma2(acc[7][3], A7, q1.y);
        }
        __syncthreads();
    }

    // shared epilogue buffers overlay As
    float* red  = &As[0][0];                  // 256 floats: [0:128] sum, [128:256] sumsq
    int*  pmaxS = (int*)(red + 256);          // 4*128
    int*  pminS = pmaxS + 512;                // 4*128
    __syncthreads();
    red[tid] = 0.f;
    pmaxS[tid] = 0; pmaxS[tid + 256] = 0;
    pminS[tid] = 0x7F800000; pminS[tid + 256] = 0x7F800000;
    __syncthreads();

    int gbase = batch[row0];
    float s[8], q[8], vmx[8], vmn[8];
#pragma unroll
    for (int j = 0; j < 8; j++) { s[j] = 0.f; q[j] = 0.f; vmx[j] = 0.f; vmn[j] = __int_as_float(0x7F800000); }
    int cur_slot = -1;
#pragma unroll
    for (int i = 0; i < 8; i++) {
        int row = row0 + ty * 8 + i;
        if (row >= Nn) continue;
        int slot = batch[row] - gbase;
        if (slot != cur_slot) {
            if (cur_slot >= 0) {  // flush
#pragma unroll
                for (int j = 0; j < 8; j++) {
                    int c = tx * 8 + j;
                    if (cur_slot < 4) {
                        atomicMax(&pmaxS[cur_slot * 128 + c], __float_as_int(vmx[j]));
                        atomicMin(&pminS[cur_slot * 128 + c], __float_as_int(vmn[j]));
                    } else {
                        atomicMax(&g_pmax[(gbase + cur_slot) * 256 + col0 + c], __float_as_int(vmx[j]));
                        atomicMin(&g_pmin[(gbase + cur_slot) * 256 + col0 + c], __float_as_int(vmn[j]));
                    }
                    vmx[j] = 0.f; vmn[j] = __int_as_float(0x7F800000);
                }
            }
            cur_slot = slot;
        }
#pragma unroll
        for (int jj = 0; jj < 4; jj++) {
            float2 v = up2(acc[i][jj]);
            int c = tx * 8 + jj * 2;
            float o0 = fmaxf(v.x + bias[col0 + c], 0.f);
            float o1 = fmaxf(v.y + bias[col0 + c + 1], 0.f);
            s[jj * 2] += o0; s[jj * 2 + 1] += o1;
            q[jj * 2] = fmaf(o0, o0, q[jj * 2]);
            q[jj * 2 + 1] = fmaf(o1, o1, q[jj * 2 + 1]);
            vmx[jj * 2] = fmaxf(vmx[jj * 2], o0); vmx[jj * 2 + 1] = fmaxf(vmx[jj * 2 + 1], o1);
            vmn[jj * 2] = fminf(vmn[jj * 2], o0); vmn[jj * 2 + 1] = fminf(vmn[jj * 2 + 1], o1);
        }
    }
    if (cur_slot >= 0) {
#pragma unroll
        for (int j = 0; j < 8; j++) {
            int c = tx * 8 + j;
            if (cur_slot < 4) {
                atomicMax(&pmaxS[cur_slot * 128 + c], __float_as_int(vmx[j]));
                atomicMin(&pminS[cur_slot * 128 + c], __float_as_int(vmn[j]));
            } else {
                atomicMax(&g_pmax[(gbase + cur_slot) * 256 + col0 + c], __float_as_int(vmx[j]));
                atomicMin(&g_pmin[(gbase + cur_slot) * 256 + col0 + c], __float_as_int(vmn[j]));
            }
        }
    }
#pragma unroll
    for (int j = 0; j < 8; j++) {
        atomicAdd(&red[tx * 8 + j], s[j]);
        atomicAdd(&red[128 + tx * 8 + j], q[j]);
    }
    __syncthreads();
    if (tid < 128) {
        atomicAdd(&sS[col0 + tid], red[tid]);
#pragma unroll
        for (int sl = 0; sl < 4; sl++) {
            int g = gbase + sl;
            if (g < Gg) {
                atomicMax(&g_pmax[g * 256 + col0 + tid], pmaxS[sl * 128 + tid]);
                atomicMin(&g_pmin[g * 256 + col0 + tid], pminS[sl * 128 + tid]);
            }
        }
    } else {
        atomicAdd(&sQ[col0 + tid - 128], red[tid]);   // FIXED: sumsq region is red[128:256]
    }
}

// ---------------- BN params, h0 materialize, pooled BN ----------------
__global__ __launch_bounds__(128) void k_bnparam(const float* __restrict__ sS,
                                                 const float* __restrict__ sQ,
                                                 const float* __restrict__ gamma,
                                                 const float* __restrict__ beta,
                                                 float* __restrict__ osc,
                                                 float* __restrict__ osh) {
    int c = threadIdx.x;
    float m = sS[c] * (1.f / Nn);
    float var = sQ[c] * (1.f / Nn) - m * m;
    float sc = gamma[c] * rsqrtf(var + EPSb);
    osc[c] = sc;
    osh[c] = beta[c] - m * sc;
}

__global__ __launch_bounds__(256) void k_h0() {
    int idx = blockIdx.x * blockDim.x + threadIdx.x;
    if (idx >= Nn * 32) return;
    int n = idx >> 5, c4 = (idx & 31) * 4;
    float4 v = *reinterpret_cast<const float4*>(&g_xcat[(size_t)n * 256 + c4]);
    float4 sc = *reinterpret_cast<const float4*>(&g_bnsc[c4]);
    float4 sh = *reinterpret_cast<const float4*>(&g_bnsh[c4]);
    float4 o;
    o.x = fmaf(v.x, sc.x, sh.x);
    o.y = fmaf(v.y, sc.y, sh.y);
    o.z = fmaf(v.z, sc.z, sh.z);
    o.w = fmaf(v.w, sc.w, sh.w);
    *reinterpret_cast<float4*>(&g_hcat2[(size_t)n * 512 + c4]) = o;
}

__global__ __launch_bounds__(256) void k_poolbn(const float* __restrict__ gammal,
                                                const float* __restrict__ betal) {
    int c = threadIdx.x;
    int g = blockIdx.x;
    float m = g_stats[512 + c] * (1.f / Nn);
    float var = g_stats[768 + c] * (1.f / Nn) - m * m;
    float sc = gammal[c] * rsqrtf(var + EPSb);
    float sh = betal[c] - m * sc;
    float vmax = __int_as_float(g_pmax[g * 256 + c]);
    float vmin = __int_as_float(g_pmin[g * 256 + c]);
    g_pooled[g * 256 + c] = (sc >= 0.f ? sc * vmax : sc * vmin) + sh;
}

// ---------------- head ----------------
__global__ __launch_bounds__(128) void k_head_gemm_relu(const float* __restrict__ A,
                                                        const float* __restrict__ B,
                                                        const float* __restrict__ bias,
                                                        float* __restrict__ Cmat,
                                                        int Kd, int Nc) {
    int idx = blockIdx.x * blockDim.x + threadIdx.x;
    if (idx >= Gg * Nc) return;
    int g = idx / Nc, c = idx - g * Nc;
    float acc = bias[c];
    for (int k = 0; k < Kd; k++) acc = fmaf(A[g * Kd + k], B[k * Nc + c], acc);
    Cmat[idx] = fmaxf(acc, 0.f);
}

__global__ __launch_bounds__(256) void k_head_bn(float* __restrict__ X,
                                                 const float* __restrict__ gamma,
                                                 const float* __restrict__ beta, int Cch) {
    int c = threadIdx.x;
    if (c >= Cch) return;
    float s = 0.f, q = 0.f;
    for (int g = 0; g < Gg; g++) {
        float v = X[g * Cch + c];
        s += v;
        q += v * v;
    }
    float m = s / Gg;
    float var = q / Gg - m * m;
    float sc = gamma[c] * rsqrtf(var + EPSb);
    float sh = beta[c] - m * sc;
    for (int g = 0; g < Gg; g++) X[g * Cch + c] = X[g * Cch + c] * sc + sh;
}

__global__ __launch_bounds__(64) void k_logits(const float* __restrict__ Wf3,
                                               const float* __restrict__ bf3,
                                               float* __restrict__ out) {
    int g = blockIdx.x;
    int c = threadIdx.x;
    __shared__ float sl[64];
    __shared__ float s_m, s_l;
    float v = -INFINITY;
    if (c < Cc) {
        float acc = bf3[c];
        for (int k = 0; k < 128; k++) acc = fmaf(g_f2[g * 128 + k], Wf3[k * Cc + c], acc);
        v = acc;
    }
    sl[c] = v;
    __syncthreads();
    if (c == 0) {
        float m = -INFINITY;
        for (int i = 0; i < Cc; i++) m = fmaxf(m, sl[i]);
        float s = 0.f;
        for (int i = 0; i < Cc; i++) s += expf(sl[i] - m);
        s_m = m;
        s_l = logf(s);
    }
    __syncthreads();
    if (c < Cc) out[g * Cc + c] = sl[c] - s_m - s_l;
}

// ---------------- launch ----------------
extern "C" void kernel_launch(void* const* d_in, const int* in_sizes, int n_in,
                              void* d_out, int out_size) {
    const float* x      = (const float*)d_in[0];
    const int*   ei     = (const int*)d_in[1];
    const float* ea     = (const float*)d_in[2];
    const int*   batch  = (const int*)d_in[3];
    const float* W1     = (const float*)d_in[4];
    const float* b1     = (const float*)d_in[5];
    const float* gamma1 = (const float*)d_in[6];
    const float* beta1  = (const float*)d_in[7];
    const float* W2     = (const float*)d_in[8];
    const float* b2     = (const float*)d_in[9];
    const float* gamma2 = (const float*)d_in[10];
    const float* beta2  = (const float*)d_in[11];
    const float* Wl     = (const float*)d_in[12];
    const float* bl     = (const float*)d_in[13];
    const float* gammal = (const float*)d_in[14];
    const float* betal  = (const float*)d_in[15];
    const float* Wf1    = (const float*)d_in[16];
    const float* bf1    = (const float*)d_in[17];
    const float* gammaf1= (const float*)d_in[18];
    const float* betaf1 = (const float*)d_in[19];
    const float* Wf2    = (const float*)d_in[20];
    const float* bf2    = (const float*)d_in[21];
    const float* gammaf2= (const float*)d_in[22];
    const float* betaf2 = (const float*)d_in[23];
    const float* Wf3    = (const float*)d_in[24];
    const float* bf3    = (const float*)d_in[25];
    const int* row = ei;
    const int* col = ei + Ee;
    float* out = (float*)d_out;

    float *p_hcat1, *p_hcat2, *p_xcat, *p_stats, *p_pooled, *p_f1, *p_f2, *p_deg, *p_bnsc, *p_bnsh;
    int *p_cnt, *p_cur, *p_pmax, *p_pmin;
    cudaGetSymbolAddress((void**)&p_hcat1, g_hcat1);
    cudaGetSymbolAddress((void**)&p_hcat2, g_hcat2);
    cudaGetSymbolAddress((void**)&p_xcat, g_xcat);
    cudaGetSymbolAddress((void**)&p_stats, g_stats);
    cudaGetSymbolAddress((void**)&p_pooled, g_pooled);
    cudaGetSymbolAddress((void**)&p_f1, g_f1);
    cudaGetSymbolAddress((void**)&p_f2, g_f2);
    cudaGetSymbolAddress((void**)&p_deg, g_deg);
    cudaGetSymbolAddress((void**)&p_bnsc, g_bnsc);
    cudaGetSymbolAddress((void**)&p_bnsh, g_bnsh);
    cudaGetSymbolAddress((void**)&p_cnt, g_cnt);
    cudaGetSymbolAddress((void**)&p_cur, g_cur);
    cudaGetSymbolAddress((void**)&p_pmax, g_pmax);
    cudaGetSymbolAddress((void**)&p_pmin, g_pmin);

    cudaMemsetAsync(p_deg, 0, Nn * sizeof(float));
    cudaMemsetAsync(p_cnt, 0, Nn * sizeof(int));
    cudaMemsetAsync(p_cur, 0, Nn * sizeof(int));
    cudaMemsetAsync(p_stats, 0, 1024 * sizeof(float));
    cudaMemsetAsync(p_pmax, 0, Gg * 256 * sizeof(int));
    cudaMemsetAsync(p_pmin, 0x7F, Gg * 256 * sizeof(int));  // 0x7F7F7F7F ~ 3.39e38

    // preprocessing: degrees -> CSR sorted by col, fused gcn_norm
    k_deg_hist<<<(Ee + 255) / 256, 256>>>(col, ea);
    k_scan<<<1, 256>>>();
    k_scatter<<<(Ee + 255) / 256, 256>>>(row, col, ea);

    // conv1
    k_copyx<<<(Nn * 16 + 255) / 256, 256>>>(x);
    k_prop<4><<<(Nn * 4 + 255) / 256, 256>>>(p_hcat1, 64, 0, 16);
    k_prop<4><<<(Nn * 4 + 255) / 256, 256>>>(p_hcat1, 64, 16, 32);
    k_prop<4><<<(Nn * 4 + 255) / 256, 256>>>(p_hcat1, 64, 32, 48);
    dim3 gconv((Nn + 127) / 128, 1);
    k_gemm_conv<<<gconv, 256>>>(p_hcat1, 64, W1, b1, p_xcat, 64, 128, p_stats, p_stats + 128);
    k_bnparam<<<1, 128>>>(p_stats, p_stats + 128, gamma1, beta1, p_bnsc, p_bnsh);
    k_h0<<<(Nn * 32 + 255) / 256, 256>>>();

    // conv2
    k_prop<32><<<(Nn * 32 + 255) / 256, 256>>>(p_hcat2, 512, 0, 128);
    k_prop<32><<<(Nn * 32 + 255) / 256, 256>>>(p_hcat2, 512, 128, 256);
    k_prop<32><<<(Nn * 32 + 255) / 256, 256>>>(p_hcat2, 512, 256, 384);
    k_gemm_conv<<<gconv, 256>>>(p_hcat2, 512, W2, b2, p_xcat + 128, 512, 128,
                                p_stats + 256, p_stats + 384);
    k_bnparam<<<1, 128>>>(p_stats + 256, p_stats + 384, gamma2, beta2, p_bnsc + 128, p_bnsh + 128);

    // lin1 fused: BN at load, relu+stats+pool in epilogue
    dim3 glin((Nn + 127) / 128, 2);
    k_gemm_lin<<<glin, 256>>>(p_xcat, Wl, bl, batch, p_stats + 512, p_stats + 768);
    k_poolbn<<<Gg, 256>>>(gammal, betal);

    // head
    k_head_gemm_relu<<<(Gg * 256 + 127) / 128, 128>>>(p_pooled, Wf1, bf1, p_f1, 256, 256);
    k_head_bn<<<1, 256>>>(p_f1, gammaf1, betaf1, 256);
    k_head_gemm_relu<<<(Gg * 128 + 127) / 128, 128>>>(p_f1, Wf2, bf2, p_f2, 256, 128);
    k_head_bn<<<1, 128>>>(p_f2, gammaf2, betaf2, 128);
    k_logits<<<Gg, 64>>>(Wf3, bf3, out);
}